// round 2
// baseline (speedup 1.0000x reference)
#include <cuda_runtime.h>
#include <math.h>

#define NJ 24
#define POSE_STRIDE (NJ * 3)
#define GROW 12            // floats per joint row: [R00 R01 R02 t0 R10 R11 R12 t1 R20 R21 R22 t2]
#define MAX_B 1024
#define NB 8               // batches per skinning block
#define VT 256             // threads (vertices) per skinning block

__constant__ int c_par[NJ] = {-1, 0, 0, 0, 1, 2, 3, 4, 5, 6, 7, 8, 9, 9, 9,
                              12, 13, 14, 16, 17, 18, 19, 20, 21};

// scratch: per-batch final transforms, 24 joints x 12 floats (no allocation)
__device__ float g_G[MAX_B * NJ * GROW];

// ---------------------------------------------------------------------------
// Kernel 1: forward kinematics. One block per batch (32 threads).
// Threads 0..23 build local [R|rel_t]; thread 0 composes the chain; threads
// 0..23 apply the rest-pose correction; all threads write to g_G.
// ---------------------------------------------------------------------------
__global__ void fk_kernel(const float* __restrict__ pose,
                          const float* __restrict__ J_hat, int B) {
    int b = blockIdx.x;
    if (b >= B) return;
    __shared__ float Gs[NJ][GROW];

    int t = threadIdx.x;
    if (t < NJ) {
        float rx = pose[b * POSE_STRIDE + t * 3 + 0];
        float ry = pose[b * POSE_STRIDE + t * 3 + 1];
        float rz = pose[b * POSE_STRIDE + t * 3 + 2];
        float theta = sqrtf(rx * rx + ry * ry + rz * rz) + 1e-8f;
        float inv = 1.0f / theta;
        float ux = rx * inv, uy = ry * inv, uz = rz * inv;
        float c = cosf(theta);
        float s = sinf(theta);
        float ic = 1.0f - c;

        int p = c_par[t];
        float jx = J_hat[t * 3 + 0];
        float jy = J_hat[t * 3 + 1];
        float jz = J_hat[t * 3 + 2];
        if (p >= 0) {
            jx -= J_hat[p * 3 + 0];
            jy -= J_hat[p * 3 + 1];
            jz -= J_hat[p * 3 + 2];
        }

        Gs[t][0]  = c + ic * ux * ux;
        Gs[t][1]  = ic * ux * uy - s * uz;
        Gs[t][2]  = ic * ux * uz + s * uy;
        Gs[t][3]  = jx;
        Gs[t][4]  = ic * uy * ux + s * uz;
        Gs[t][5]  = c + ic * uy * uy;
        Gs[t][6]  = ic * uy * uz - s * ux;
        Gs[t][7]  = jy;
        Gs[t][8]  = ic * uz * ux - s * uy;
        Gs[t][9]  = ic * uz * uy + s * ux;
        Gs[t][10] = c + ic * uz * uz;
        Gs[t][11] = jz;
    }
    __syncthreads();

    if (t == 0) {
        // sequential chain compose: parents always precede children
        for (int i = 1; i < NJ; i++) {
            int p = c_par[i];
            float tmp[GROW];
            #pragma unroll
            for (int x = 0; x < 3; x++) {
                float p0 = Gs[p][x * 4 + 0];
                float p1 = Gs[p][x * 4 + 1];
                float p2 = Gs[p][x * 4 + 2];
                float p3 = Gs[p][x * 4 + 3];
                tmp[x * 4 + 0] = p0 * Gs[i][0] + p1 * Gs[i][4] + p2 * Gs[i][8];
                tmp[x * 4 + 1] = p0 * Gs[i][1] + p1 * Gs[i][5] + p2 * Gs[i][9];
                tmp[x * 4 + 2] = p0 * Gs[i][2] + p1 * Gs[i][6] + p2 * Gs[i][10];
                tmp[x * 4 + 3] = p0 * Gs[i][3] + p1 * Gs[i][7] + p2 * Gs[i][11] + p3;
            }
            #pragma unroll
            for (int k = 0; k < GROW; k++) Gs[i][k] = tmp[k];
        }
    }
    __syncthreads();

    if (t < NJ) {
        // rest-pose correction: t' = t - R @ J_hat[j]
        float jx = J_hat[t * 3 + 0];
        float jy = J_hat[t * 3 + 1];
        float jz = J_hat[t * 3 + 2];
        Gs[t][3]  -= Gs[t][0] * jx + Gs[t][1]  * jy + Gs[t][2]  * jz;
        Gs[t][7]  -= Gs[t][4] * jx + Gs[t][5]  * jy + Gs[t][6]  * jz;
        Gs[t][11] -= Gs[t][8] * jx + Gs[t][9]  * jy + Gs[t][10] * jz;
    }
    __syncthreads();

    const float* src = &Gs[0][0];
    float* dst = g_G + (size_t)b * NJ * GROW;
    for (int i = t; i < NJ * GROW; i += blockDim.x) dst[i] = src[i];
}

// ---------------------------------------------------------------------------
// Kernel 2: linear blend skinning. Block = VT vertices x NB batches.
// Weights row kept in registers, reused for all NB batches. G in SMEM,
// read via broadcast float4 loads.
// ---------------------------------------------------------------------------
__global__ __launch_bounds__(VT)
void skin_kernel(const float* __restrict__ T_hat,
                 const float* __restrict__ W,
                 const float* __restrict__ trans,
                 float* __restrict__ out, int V, int B) {
    __shared__ float4 Gs4[NB * NJ * 3];   // NB batches x 24 joints x 12 floats
    __shared__ float  ts[NB * 3];

    int b0 = blockIdx.y * NB;
    int nb = min(NB, B - b0);

    // cooperative load of G for this batch group (1152 B/batch, 16B aligned)
    {
        const float4* gsrc = reinterpret_cast<const float4*>(g_G + (size_t)b0 * NJ * GROW);
        int n4 = nb * NJ * 3;
        for (int i = threadIdx.x; i < n4; i += VT) Gs4[i] = gsrc[i];
        if (threadIdx.x < nb * 3) ts[threadIdx.x] = trans[b0 * 3 + threadIdx.x];
    }
    __syncthreads();

    int v = blockIdx.x * VT + threadIdx.x;
    if (v >= V) return;

    // per-vertex weights (24 floats, row stride 96 B -> 16B aligned)
    float w[NJ];
    {
        const float4* w4 = reinterpret_cast<const float4*>(W + (size_t)v * NJ);
        #pragma unroll
        for (int q = 0; q < NJ / 4; q++) {
            float4 f = w4[q];
            w[q * 4 + 0] = f.x; w[q * 4 + 1] = f.y;
            w[q * 4 + 2] = f.z; w[q * 4 + 3] = f.w;
        }
    }
    float px = T_hat[v * 3 + 0];
    float py = T_hat[v * 3 + 1];
    float pz = T_hat[v * 3 + 2];

    for (int bb = 0; bb < nb; bb++) {
        float a[GROW];
        #pragma unroll
        for (int k = 0; k < GROW; k++) a[k] = 0.0f;

        const float4* g = Gs4 + bb * NJ * 3;
        #pragma unroll
        for (int j = 0; j < NJ; j++) {
            float wj = w[j];
            float4 g0 = g[j * 3 + 0];
            float4 g1 = g[j * 3 + 1];
            float4 g2 = g[j * 3 + 2];
            a[0]  += wj * g0.x; a[1]  += wj * g0.y; a[2]  += wj * g0.z; a[3]  += wj * g0.w;
            a[4]  += wj * g1.x; a[5]  += wj * g1.y; a[6]  += wj * g1.z; a[7]  += wj * g1.w;
            a[8]  += wj * g2.x; a[9]  += wj * g2.y; a[10] += wj * g2.z; a[11] += wj * g2.w;
        }

        float ox = a[0] * px + a[1] * py + a[2]  * pz + a[3]  + ts[bb * 3 + 0];
        float oy = a[4] * px + a[5] * py + a[6]  * pz + a[7]  + ts[bb * 3 + 1];
        float oz = a[8] * px + a[9] * py + a[10] * pz + a[11] + ts[bb * 3 + 2];

        float* o = out + ((size_t)(b0 + bb) * V + v) * 3;
        o[0] = ox; o[1] = oy; o[2] = oz;
    }
}

// ---------------------------------------------------------------------------
// Launch: pure kernel launches, nothing else (graph-capture safe).
// ---------------------------------------------------------------------------
extern "C" void kernel_launch(void* const* d_in, const int* in_sizes, int n_in,
                              void* d_out, int out_size) {
    const float* T_hat   = (const float*)d_in[0];   // (V,3)
    const float* J_hat   = (const float*)d_in[1];   // (24,3)
    const float* weights = (const float*)d_in[2];   // (V,24)
    const float* pose    = (const float*)d_in[3];   // (B,72)
    const float* trans   = (const float*)d_in[4];   // (B,3)
    float* out = (float*)d_out;

    int V = in_sizes[0] / 3;
    int B = in_sizes[3] / POSE_STRIDE;
    if (B > MAX_B) B = MAX_B;

    fk_kernel<<<B, 32>>>(pose, J_hat, B);

    dim3 grid((V + VT - 1) / VT, (B + NB - 1) / NB);
    skin_kernel<<<grid, VT>>>(T_hat, weights, trans, out, V, B);
}

// round 4
// speedup vs baseline: 1.2287x; 1.2287x over previous
#include <cuda_runtime.h>
#include <math.h>
#include <stdint.h>

#define NJ 24
#define POSE_STRIDE (NJ * 3)
#define GROW 12            // floats per joint: [R00 R01 R02 t0 | R10 R11 R12 t1 | R20 R21 R22 t2]
#define MAX_B 1024
#define NB 8               // batches per skinning block
#define VT 256             // threads per skinning block
#define VPT 2              // vertices per thread

__constant__ int c_par[NJ] = {-1, 0, 0, 0, 1, 2, 3, 4, 5, 6, 7, 8, 9, 9, 9,
                              12, 13, 14, 16, 17, 18, 19, 20, 21};

// scratch: per-batch final transforms, 24 joints x 12 floats (no allocation)
__device__ float g_G[MAX_B * NJ * GROW];

// ---------------- packed f32x2 helpers (sm_100-family only) ----------------
__device__ __forceinline__ uint64_t packf2(float lo, float hi) {
    uint64_t r;
    asm("mov.b64 %0, {%1, %2};" : "=l"(r) : "f"(lo), "f"(hi));
    return r;
}
__device__ __forceinline__ void fma2(uint64_t& a, uint64_t b, uint64_t c) {
    // a = b * c + a  (two independent fp32 lanes)
    asm("fma.rn.f32x2 %0, %1, %2, %0;" : "+l"(a) : "l"(b), "l"(c));
}
__device__ __forceinline__ void unpackf2(uint64_t p, float& lo, float& hi) {
    asm("mov.b64 {%0, %1}, %2;" : "=f"(lo), "=f"(hi) : "l"(p));
}

// ---------------------------------------------------------------------------
// Kernel 1: forward kinematics. One block per batch (32 threads).
// ---------------------------------------------------------------------------
__global__ void fk_kernel(const float* __restrict__ pose,
                          const float* __restrict__ J_hat, int B) {
    int b = blockIdx.x;
    if (b >= B) return;
    __shared__ float Gs[NJ][GROW];

    int t = threadIdx.x;
    if (t < NJ) {
        float rx = pose[b * POSE_STRIDE + t * 3 + 0];
        float ry = pose[b * POSE_STRIDE + t * 3 + 1];
        float rz = pose[b * POSE_STRIDE + t * 3 + 2];
        float theta = sqrtf(rx * rx + ry * ry + rz * rz) + 1e-8f;
        float inv = 1.0f / theta;
        float ux = rx * inv, uy = ry * inv, uz = rz * inv;
        float c = cosf(theta);
        float s = sinf(theta);
        float ic = 1.0f - c;

        int p = c_par[t];
        float jx = J_hat[t * 3 + 0];
        float jy = J_hat[t * 3 + 1];
        float jz = J_hat[t * 3 + 2];
        if (p >= 0) {
            jx -= J_hat[p * 3 + 0];
            jy -= J_hat[p * 3 + 1];
            jz -= J_hat[p * 3 + 2];
        }

        Gs[t][0]  = c + ic * ux * ux;
        Gs[t][1]  = ic * ux * uy - s * uz;
        Gs[t][2]  = ic * ux * uz + s * uy;
        Gs[t][3]  = jx;
        Gs[t][4]  = ic * uy * ux + s * uz;
        Gs[t][5]  = c + ic * uy * uy;
        Gs[t][6]  = ic * uy * uz - s * ux;
        Gs[t][7]  = jy;
        Gs[t][8]  = ic * uz * ux - s * uy;
        Gs[t][9]  = ic * uz * uy + s * ux;
        Gs[t][10] = c + ic * uz * uz;
        Gs[t][11] = jz;
    }
    __syncthreads();

    if (t == 0) {
        for (int i = 1; i < NJ; i++) {
            int p = c_par[i];
            float tmp[GROW];
            #pragma unroll
            for (int x = 0; x < 3; x++) {
                float p0 = Gs[p][x * 4 + 0];
                float p1 = Gs[p][x * 4 + 1];
                float p2 = Gs[p][x * 4 + 2];
                float p3 = Gs[p][x * 4 + 3];
                tmp[x * 4 + 0] = p0 * Gs[i][0] + p1 * Gs[i][4] + p2 * Gs[i][8];
                tmp[x * 4 + 1] = p0 * Gs[i][1] + p1 * Gs[i][5] + p2 * Gs[i][9];
                tmp[x * 4 + 2] = p0 * Gs[i][2] + p1 * Gs[i][6] + p2 * Gs[i][10];
                tmp[x * 4 + 3] = p0 * Gs[i][3] + p1 * Gs[i][7] + p2 * Gs[i][11] + p3;
            }
            #pragma unroll
            for (int k = 0; k < GROW; k++) Gs[i][k] = tmp[k];
        }
    }
    __syncthreads();

    if (t < NJ) {
        float jx = J_hat[t * 3 + 0];
        float jy = J_hat[t * 3 + 1];
        float jz = J_hat[t * 3 + 2];
        Gs[t][3]  -= Gs[t][0] * jx + Gs[t][1]  * jy + Gs[t][2]  * jz;
        Gs[t][7]  -= Gs[t][4] * jx + Gs[t][5]  * jy + Gs[t][6]  * jz;
        Gs[t][11] -= Gs[t][8] * jx + Gs[t][9]  * jy + Gs[t][10] * jz;
    }
    __syncthreads();

    const float* src = &Gs[0][0];
    float* dst = g_G + (size_t)b * NJ * GROW;
    for (int i = t; i < NJ * GROW; i += blockDim.x) dst[i] = src[i];
}

// ---------------------------------------------------------------------------
// Kernel 2: LBS. Block covers VT*VPT vertices x NB batches.
// G in SMEM as 64-bit pairs; accumulation in packed fma.rn.f32x2;
// each SMEM load amortized over VPT vertices.
// ---------------------------------------------------------------------------
__global__ __launch_bounds__(VT)
void skin_kernel(const float* __restrict__ T_hat,
                 const float* __restrict__ W,
                 const float* __restrict__ trans,
                 float* __restrict__ out, int V, int B) {
    __shared__ ulonglong2 Gs[NB * NJ * 3];   // NB x 24 joints x 12 floats (16B chunks)
    __shared__ float ts[NB * 3];

    int b0 = blockIdx.y * NB;
    int nb = min(NB, B - b0);

    {
        const ulonglong2* gsrc =
            reinterpret_cast<const ulonglong2*>(g_G + (size_t)b0 * NJ * GROW);
        int n = nb * NJ * 3;
        for (int i = threadIdx.x; i < n; i += VT) Gs[i] = gsrc[i];
        if (threadIdx.x < nb * 3) ts[threadIdx.x] = trans[b0 * 3 + threadIdx.x];
    }
    __syncthreads();

    int v0 = blockIdx.x * (VT * VPT) + threadIdx.x;
    int v1 = v0 + VT;
    bool ok0 = v0 < V;
    bool ok1 = v1 < V;
    if (!ok0) return;                 // v1 > v0, so nothing to do
    int vc1 = ok1 ? v1 : v0;          // clamp reads for inactive second vertex

    // per-vertex weights (24 floats, row stride 96 B -> 16B aligned)
    float w0[NJ], w1[NJ];
    {
        const float4* a4 = reinterpret_cast<const float4*>(W + (size_t)v0 * NJ);
        const float4* b4 = reinterpret_cast<const float4*>(W + (size_t)vc1 * NJ);
        #pragma unroll
        for (int q = 0; q < NJ / 4; q++) {
            float4 fa = a4[q];
            w0[q * 4 + 0] = fa.x; w0[q * 4 + 1] = fa.y;
            w0[q * 4 + 2] = fa.z; w0[q * 4 + 3] = fa.w;
            float4 fb = b4[q];
            w1[q * 4 + 0] = fb.x; w1[q * 4 + 1] = fb.y;
            w1[q * 4 + 2] = fb.z; w1[q * 4 + 3] = fb.w;
        }
    }
    float p0x = T_hat[v0 * 3 + 0], p0y = T_hat[v0 * 3 + 1], p0z = T_hat[v0 * 3 + 2];
    float p1x = T_hat[vc1 * 3 + 0], p1y = T_hat[vc1 * 3 + 1], p1z = T_hat[vc1 * 3 + 2];

    for (int bb = 0; bb < nb; bb++) {
        uint64_t acc0[6], acc1[6];
        #pragma unroll
        for (int k = 0; k < 6; k++) { acc0[k] = 0ull; acc1[k] = 0ull; }

        const ulonglong2* g = Gs + bb * NJ * 3;
        #pragma unroll
        for (int j = 0; j < NJ; j++) {
            uint64_t wa = packf2(w0[j], w0[j]);
            uint64_t wb = packf2(w1[j], w1[j]);
            ulonglong2 q0 = g[j * 3 + 0];   // floats 0..3
            ulonglong2 q1 = g[j * 3 + 1];   // floats 4..7
            ulonglong2 q2 = g[j * 3 + 2];   // floats 8..11
            fma2(acc0[0], q0.x, wa); fma2(acc1[0], q0.x, wb);
            fma2(acc0[1], q0.y, wa); fma2(acc1[1], q0.y, wb);
            fma2(acc0[2], q1.x, wa); fma2(acc1[2], q1.x, wb);
            fma2(acc0[3], q1.y, wa); fma2(acc1[3], q1.y, wb);
            fma2(acc0[4], q2.x, wa); fma2(acc1[4], q2.x, wb);
            fma2(acc0[5], q2.y, wa); fma2(acc1[5], q2.y, wb);
        }

        float tx = ts[bb * 3 + 0], ty = ts[bb * 3 + 1], tz = ts[bb * 3 + 2];

        // vertex 0 epilogue
        {
            float a0, a1, a2, a3, a4, a5, a6, a7, a8, a9, a10, a11;
            unpackf2(acc0[0], a0, a1);  unpackf2(acc0[1], a2, a3);
            unpackf2(acc0[2], a4, a5);  unpackf2(acc0[3], a6, a7);
            unpackf2(acc0[4], a8, a9);  unpackf2(acc0[5], a10, a11);
            float ox = a0 * p0x + a1 * p0y + a2  * p0z + a3  + tx;
            float oy = a4 * p0x + a5 * p0y + a6  * p0z + a7  + ty;
            float oz = a8 * p0x + a9 * p0y + a10 * p0z + a11 + tz;
            float* o = out + ((size_t)(b0 + bb) * V + v0) * 3;
            o[0] = ox; o[1] = oy; o[2] = oz;
        }
        // vertex 1 epilogue
        if (ok1) {
            float a0, a1, a2, a3, a4, a5, a6, a7, a8, a9, a10, a11;
            unpackf2(acc1[0], a0, a1);  unpackf2(acc1[1], a2, a3);
            unpackf2(acc1[2], a4, a5);  unpackf2(acc1[3], a6, a7);
            unpackf2(acc1[4], a8, a9);  unpackf2(acc1[5], a10, a11);
            float ox = a0 * p1x + a1 * p1y + a2  * p1z + a3  + tx;
            float oy = a4 * p1x + a5 * p1y + a6  * p1z + a7  + ty;
            float oz = a8 * p1x + a9 * p1y + a10 * p1z + a11 + tz;
            float* o = out + ((size_t)(b0 + bb) * V + v1) * 3;
            o[0] = ox; o[1] = oy; o[2] = oz;
        }
    }
}

// ---------------------------------------------------------------------------
// Launch: pure kernel launches only (graph-capture safe).
// ---------------------------------------------------------------------------
extern "C" void kernel_launch(void* const* d_in, const int* in_sizes, int n_in,
                              void* d_out, int out_size) {
    const float* T_hat   = (const float*)d_in[0];   // (V,3)
    const float* J_hat   = (const float*)d_in[1];   // (24,3)
    const float* weights = (const float*)d_in[2];   // (V,24)
    const float* pose    = (const float*)d_in[3];   // (B,72)
    const float* trans   = (const float*)d_in[4];   // (B,3)
    float* out = (float*)d_out;

    int V = in_sizes[0] / 3;
    int B = in_sizes[3] / POSE_STRIDE;
    if (B > MAX_B) B = MAX_B;

    fk_kernel<<<B, 32>>>(pose, J_hat, B);

    dim3 grid((V + VT * VPT - 1) / (VT * VPT), (B + NB - 1) / NB);
    skin_kernel<<<grid, VT>>>(T_hat, weights, trans, out, V, B);
}

// round 6
// speedup vs baseline: 1.4199x; 1.1556x over previous
#include <cuda_runtime.h>
#include <math.h>
#include <stdint.h>

#define NJ 24
#define POSE_STRIDE (NJ * 3)
#define GROW 12            // floats per joint: [R00 R01 R02 t0 | R10 R11 R12 t1 | R20 R21 R22 t2]
#define MAX_B 1024
#define NB 8               // batches per skinning block
#define VT 128             // threads per skinning block (smaller block -> 5 CTAs/SM at 96 regs)
#define VPT 2              // vertices per thread

__constant__ int c_par[NJ] = {-1, 0, 0, 0, 1, 2, 3, 4, 5, 6, 7, 8, 9, 9, 9,
                              12, 13, 14, 16, 17, 18, 19, 20, 21};

// scratch: per-batch final transforms, 24 joints x 12 floats (no allocation)
__device__ float g_G[MAX_B * NJ * GROW];

// ---------------- packed f32x2 helpers (sm_100-family only) ----------------
__device__ __forceinline__ uint64_t packf2(float lo, float hi) {
    uint64_t r;
    asm("mov.b64 %0, {%1, %2};" : "=l"(r) : "f"(lo), "f"(hi));
    return r;
}
__device__ __forceinline__ void fma2(uint64_t& a, uint64_t b, uint64_t c) {
    // a = b * c + a  (two independent fp32 lanes)
    asm("fma.rn.f32x2 %0, %1, %2, %0;" : "+l"(a) : "l"(b), "l"(c));
}
__device__ __forceinline__ void unpackf2(uint64_t p, float& lo, float& hi) {
    asm("mov.b64 {%0, %1}, %2;" : "=f"(lo), "=f"(hi) : "l"(p));
}

// ---------------------------------------------------------------------------
// Kernel 1: forward kinematics. One block per batch (32 threads).
// ---------------------------------------------------------------------------
__global__ void fk_kernel(const float* __restrict__ pose,
                          const float* __restrict__ J_hat, int B) {
    int b = blockIdx.x;
    if (b >= B) return;
    __shared__ float Gs[NJ][GROW];

    int t = threadIdx.x;
    if (t < NJ) {
        float rx = pose[b * POSE_STRIDE + t * 3 + 0];
        float ry = pose[b * POSE_STRIDE + t * 3 + 1];
        float rz = pose[b * POSE_STRIDE + t * 3 + 2];
        float theta = sqrtf(rx * rx + ry * ry + rz * rz) + 1e-8f;
        float inv = 1.0f / theta;
        float ux = rx * inv, uy = ry * inv, uz = rz * inv;
        float c = cosf(theta);
        float s = sinf(theta);
        float ic = 1.0f - c;

        int p = c_par[t];
        float jx = J_hat[t * 3 + 0];
        float jy = J_hat[t * 3 + 1];
        float jz = J_hat[t * 3 + 2];
        if (p >= 0) {
            jx -= J_hat[p * 3 + 0];
            jy -= J_hat[p * 3 + 1];
            jz -= J_hat[p * 3 + 2];
        }

        Gs[t][0]  = c + ic * ux * ux;
        Gs[t][1]  = ic * ux * uy - s * uz;
        Gs[t][2]  = ic * ux * uz + s * uy;
        Gs[t][3]  = jx;
        Gs[t][4]  = ic * uy * ux + s * uz;
        Gs[t][5]  = c + ic * uy * uy;
        Gs[t][6]  = ic * uy * uz - s * ux;
        Gs[t][7]  = jy;
        Gs[t][8]  = ic * uz * ux - s * uy;
        Gs[t][9]  = ic * uz * uy + s * ux;
        Gs[t][10] = c + ic * uz * uz;
        Gs[t][11] = jz;
    }
    __syncthreads();

    if (t == 0) {
        for (int i = 1; i < NJ; i++) {
            int p = c_par[i];
            float tmp[GROW];
            #pragma unroll
            for (int x = 0; x < 3; x++) {
                float p0 = Gs[p][x * 4 + 0];
                float p1 = Gs[p][x * 4 + 1];
                float p2 = Gs[p][x * 4 + 2];
                float p3 = Gs[p][x * 4 + 3];
                tmp[x * 4 + 0] = p0 * Gs[i][0] + p1 * Gs[i][4] + p2 * Gs[i][8];
                tmp[x * 4 + 1] = p0 * Gs[i][1] + p1 * Gs[i][5] + p2 * Gs[i][9];
                tmp[x * 4 + 2] = p0 * Gs[i][2] + p1 * Gs[i][6] + p2 * Gs[i][10];
                tmp[x * 4 + 3] = p0 * Gs[i][3] + p1 * Gs[i][7] + p2 * Gs[i][11] + p3;
            }
            #pragma unroll
            for (int k = 0; k < GROW; k++) Gs[i][k] = tmp[k];
        }
    }
    __syncthreads();

    if (t < NJ) {
        float jx = J_hat[t * 3 + 0];
        float jy = J_hat[t * 3 + 1];
        float jz = J_hat[t * 3 + 2];
        Gs[t][3]  -= Gs[t][0] * jx + Gs[t][1]  * jy + Gs[t][2]  * jz;
        Gs[t][7]  -= Gs[t][4] * jx + Gs[t][5]  * jy + Gs[t][6]  * jz;
        Gs[t][11] -= Gs[t][8] * jx + Gs[t][9]  * jy + Gs[t][10] * jz;
    }
    __syncthreads();

    const float* src = &Gs[0][0];
    float* dst = g_G + (size_t)b * NJ * GROW;
    for (int i = t; i < NJ * GROW; i += blockDim.x) dst[i] = src[i];
}

// ---------------------------------------------------------------------------
// Kernel 2: LBS. Block covers VT*VPT vertices x NB batches.
// G in SMEM as 64-bit pairs; accumulation in packed fma.rn.f32x2;
// each SMEM load amortized over VPT vertices.
// ---------------------------------------------------------------------------
__global__ __launch_bounds__(VT)
void skin_kernel(const float* __restrict__ T_hat,
                 const float* __restrict__ W,
                 const float* __restrict__ trans,
                 float* __restrict__ out, int V, int B) {
    __shared__ ulonglong2 Gs[NB * NJ * 3];   // NB x 24 joints x 12 floats (16B chunks)
    __shared__ float ts[NB * 3];

    int b0 = blockIdx.y * NB;
    int nb = min(NB, B - b0);

    {
        const ulonglong2* gsrc =
            reinterpret_cast<const ulonglong2*>(g_G + (size_t)b0 * NJ * GROW);
        int n = nb * NJ * 3;
        for (int i = threadIdx.x; i < n; i += VT) Gs[i] = gsrc[i];
        if (threadIdx.x < nb * 3) ts[threadIdx.x] = trans[b0 * 3 + threadIdx.x];
    }
    __syncthreads();

    int v0 = blockIdx.x * (VT * VPT) + threadIdx.x;
    int v1 = v0 + VT;
    bool ok0 = v0 < V;
    bool ok1 = v1 < V;
    if (!ok0) return;                 // v1 > v0, so nothing to do
    int vc1 = ok1 ? v1 : v0;          // clamp reads for inactive second vertex

    // per-vertex weights (24 floats, row stride 96 B -> 16B aligned)
    float w0[NJ], w1[NJ];
    {
        const float4* a4 = reinterpret_cast<const float4*>(W + (size_t)v0 * NJ);
        const float4* b4 = reinterpret_cast<const float4*>(W + (size_t)vc1 * NJ);
        #pragma unroll
        for (int q = 0; q < NJ / 4; q++) {
            float4 fa = a4[q];
            w0[q * 4 + 0] = fa.x; w0[q * 4 + 1] = fa.y;
            w0[q * 4 + 2] = fa.z; w0[q * 4 + 3] = fa.w;
            float4 fb = b4[q];
            w1[q * 4 + 0] = fb.x; w1[q * 4 + 1] = fb.y;
            w1[q * 4 + 2] = fb.z; w1[q * 4 + 3] = fb.w;
        }
    }
    float p0x = T_hat[v0 * 3 + 0], p0y = T_hat[v0 * 3 + 1], p0z = T_hat[v0 * 3 + 2];
    float p1x = T_hat[vc1 * 3 + 0], p1y = T_hat[vc1 * 3 + 1], p1z = T_hat[vc1 * 3 + 2];

    for (int bb = 0; bb < nb; bb++) {
        uint64_t acc0[6], acc1[6];
        #pragma unroll
        for (int k = 0; k < 6; k++) { acc0[k] = 0ull; acc1[k] = 0ull; }

        const ulonglong2* g = Gs + bb * NJ * 3;
        #pragma unroll
        for (int j = 0; j < NJ; j++) {
            uint64_t wa = packf2(w0[j], w0[j]);
            uint64_t wb = packf2(w1[j], w1[j]);
            ulonglong2 q0 = g[j * 3 + 0];   // floats 0..3
            ulonglong2 q1 = g[j * 3 + 1];   // floats 4..7
            ulonglong2 q2 = g[j * 3 + 2];   // floats 8..11
            fma2(acc0[0], q0.x, wa); fma2(acc1[0], q0.x, wb);
            fma2(acc0[1], q0.y, wa); fma2(acc1[1], q0.y, wb);
            fma2(acc0[2], q1.x, wa); fma2(acc1[2], q1.x, wb);
            fma2(acc0[3], q1.y, wa); fma2(acc1[3], q1.y, wb);
            fma2(acc0[4], q2.x, wa); fma2(acc1[4], q2.x, wb);
            fma2(acc0[5], q2.y, wa); fma2(acc1[5], q2.y, wb);
        }

        float tx = ts[bb * 3 + 0], ty = ts[bb * 3 + 1], tz = ts[bb * 3 + 2];

        // vertex 0 epilogue
        {
            float a0, a1, a2, a3, a4, a5, a6, a7, a8, a9, a10, a11;
            unpackf2(acc0[0], a0, a1);  unpackf2(acc0[1], a2, a3);
            unpackf2(acc0[2], a4, a5);  unpackf2(acc0[3], a6, a7);
            unpackf2(acc0[4], a8, a9);  unpackf2(acc0[5], a10, a11);
            float ox = a0 * p0x + a1 * p0y + a2  * p0z + a3  + tx;
            float oy = a4 * p0x + a5 * p0y + a6  * p0z + a7  + ty;
            float oz = a8 * p0x + a9 * p0y + a10 * p0z + a11 + tz;
            float* o = out + ((size_t)(b0 + bb) * V + v0) * 3;
            o[0] = ox; o[1] = oy; o[2] = oz;
        }
        // vertex 1 epilogue
        if (ok1) {
            float a0, a1, a2, a3, a4, a5, a6, a7, a8, a9, a10, a11;
            unpackf2(acc1[0], a0, a1);  unpackf2(acc1[1], a2, a3);
            unpackf2(acc1[2], a4, a5);  unpackf2(acc1[3], a6, a7);
            unpackf2(acc1[4], a8, a9);  unpackf2(acc1[5], a10, a11);
            float ox = a0 * p1x + a1 * p1y + a2  * p1z + a3  + tx;
            float oy = a4 * p1x + a5 * p1y + a6  * p1z + a7  + ty;
            float oz = a8 * p1x + a9 * p1y + a10 * p1z + a11 + tz;
            float* o = out + ((size_t)(b0 + bb) * V + v1) * 3;
            o[0] = ox; o[1] = oy; o[2] = oz;
        }
    }
}

// ---------------------------------------------------------------------------
// Launch: pure kernel launches only (graph-capture safe).
// ---------------------------------------------------------------------------
extern "C" void kernel_launch(void* const* d_in, const int* in_sizes, int n_in,
                              void* d_out, int out_size) {
    const float* T_hat   = (const float*)d_in[0];   // (V,3)
    const float* J_hat   = (const float*)d_in[1];   // (24,3)
    const float* weights = (const float*)d_in[2];   // (V,24)
    const float* pose    = (const float*)d_in[3];   // (B,72)
    const float* trans   = (const float*)d_in[4];   // (B,3)
    float* out = (float*)d_out;

    int V = in_sizes[0] / 3;
    int B = in_sizes[3] / POSE_STRIDE;
    if (B > MAX_B) B = MAX_B;

    fk_kernel<<<B, 32>>>(pose, J_hat, B);

    dim3 grid((V + VT * VPT - 1) / (VT * VPT), (B + NB - 1) / NB);
    skin_kernel<<<grid, VT>>>(T_hat, weights, trans, out, V, B);
}